// round 3
// baseline (speedup 1.0000x reference)
#include <cuda_runtime.h>

// Problem constants (fixed by the dataset)
#define BB    2
#define SS    1024
#define NBLK  64
#define DIM   256
#define NH    8
#define DHD   32
#define NROWS (BB * SS * NBLK)   // 131072

// ---------------------------------------------------------------------------
// Scratch for projected Q/K/V (allocation-free rule: __device__ globals).
// ---------------------------------------------------------------------------
__device__ float g_Q[NROWS * DIM];
__device__ float g_K[NROWS * DIM];
__device__ float g_V[NROWS * DIM];

// ---------------------------------------------------------------------------
// Packed f32x2 helpers (sm_103a FFMA2 path: 2 fp32 FMAs per instruction)
// ---------------------------------------------------------------------------
__device__ __forceinline__ unsigned long long pack2(float x, float y) {
    unsigned long long r;
    asm("mov.b64 %0, {%1, %2};" : "=l"(r) : "f"(x), "f"(y));
    return r;
}
__device__ __forceinline__ void unpack2(unsigned long long v, float& x, float& y) {
    asm("mov.b64 {%0, %1}, %2;" : "=f"(x), "=f"(y) : "l"(v));
}
__device__ __forceinline__ void ffma2(unsigned long long& d, unsigned long long a,
                                      unsigned long long b) {
    asm("fma.rn.f32x2 %0, %1, %2, %0;" : "+l"(d) : "l"(a), "l"(b));
}

// ---------------------------------------------------------------------------
// Projection GEMM:  C[n, j] = sum_k X[n, k] * W[j, k] + bias[j]
// Tiles: BM=128 rows x BN=128 cols x BK=32, 256 threads, 8x8 per thread.
// Accumulators are f32x2 pairs along the j (column) axis; the b-operand
// pairs are contiguous in smem (loaded as 64-bit), a-operand duplicated once.
// ---------------------------------------------------------------------------
#define BM 128
#define BN 128
#define BK 32

__global__ __launch_bounds__(256)
void proj_gemm(const float* __restrict__ X, const float* __restrict__ W,
               const float* __restrict__ bias, int which)
{
    __shared__ __align__(16) float Xs[BK][BM];
    __shared__ __align__(16) float Ws[BK][BN];

    float* C = (which == 0) ? g_Q : (which == 1) ? g_K : g_V;

    const int tid = threadIdx.x;
    const int ty  = tid >> 4;          // 0..15 (row group of 8)
    const int tx  = tid & 15;          // 0..15 (col group of 8)
    const int rowBase = blockIdx.y * BM;
    const int colBase = blockIdx.x * BN;

    const int ldRow = tid >> 3;        // 0..31
    const int ldK   = (tid & 7) * 4;   // 0,4,...,28

    unsigned long long acc[8][4];
    #pragma unroll
    for (int i = 0; i < 8; i++)
        #pragma unroll
        for (int j = 0; j < 4; j++) acc[i][j] = 0ULL;

    for (int kb = 0; kb < DIM; kb += BK) {
        // Stage X and W tiles transposed: [k][row]
        #pragma unroll
        for (int i = 0; i < 4; i++) {
            int r = ldRow + i * 32;
            float4 xv = *(const float4*)&X[(rowBase + r) * DIM + kb + ldK];
            Xs[ldK + 0][r] = xv.x; Xs[ldK + 1][r] = xv.y;
            Xs[ldK + 2][r] = xv.z; Xs[ldK + 3][r] = xv.w;
            float4 wv = *(const float4*)&W[(colBase + r) * DIM + kb + ldK];
            Ws[ldK + 0][r] = wv.x; Ws[ldK + 1][r] = wv.y;
            Ws[ldK + 2][r] = wv.z; Ws[ldK + 3][r] = wv.w;
        }
        __syncthreads();

        #pragma unroll
        for (int k = 0; k < BK; k++) {
            float4 a0 = *(const float4*)&Xs[k][ty * 8];
            float4 a1 = *(const float4*)&Xs[k][ty * 8 + 4];
            ulonglong2 b0 = *(const ulonglong2*)&Ws[k][tx * 8];
            ulonglong2 b1 = *(const ulonglong2*)&Ws[k][tx * 8 + 4];
            unsigned long long aa[8];
            aa[0] = pack2(a0.x, a0.x); aa[1] = pack2(a0.y, a0.y);
            aa[2] = pack2(a0.z, a0.z); aa[3] = pack2(a0.w, a0.w);
            aa[4] = pack2(a1.x, a1.x); aa[5] = pack2(a1.y, a1.y);
            aa[6] = pack2(a1.z, a1.z); aa[7] = pack2(a1.w, a1.w);
            #pragma unroll
            for (int i = 0; i < 8; i++) {
                ffma2(acc[i][0], aa[i], b0.x);
                ffma2(acc[i][1], aa[i], b0.y);
                ffma2(acc[i][2], aa[i], b1.x);
                ffma2(acc[i][3], aa[i], b1.y);
            }
        }
        __syncthreads();
    }

    // Epilogue: + bias, store
    float bl[8];
    #pragma unroll
    for (int j = 0; j < 8; j++) bl[j] = bias[colBase + tx * 8 + j];

    #pragma unroll
    for (int i = 0; i < 8; i++) {
        int r = rowBase + ty * 8 + i;
        float o[8];
        #pragma unroll
        for (int j = 0; j < 4; j++) unpack2(acc[i][j], o[2 * j], o[2 * j + 1]);
        #pragma unroll
        for (int j = 0; j < 8; j++) o[j] += bl[j];
        *(float4*)&C[r * DIM + colBase + tx * 8]     = make_float4(o[0], o[1], o[2], o[3]);
        *(float4*)&C[r * DIM + colBase + tx * 8 + 4] = make_float4(o[4], o[5], o[6], o[7]);
    }
}

// ---------------------------------------------------------------------------
// Block attention: one CTA per (b, s). Q/V row-major in smem, K transposed
// (Kt[d][m]) so the score microkernel reads conflict-free float4s along m.
// ---------------------------------------------------------------------------
#define QST  260                        // Q/V smem row stride (floats)
#define KTST 68                         // Kt row stride
#define PST  68                         // P row stride
#define SM_QS 0
#define SM_KT (64 * QST)                // 16640
#define SM_VS (SM_KT + DIM * KTST)      // 34048
#define SM_PS (SM_VS + 64 * QST)        // 50688
#define SM_TOT_FLOATS (SM_PS + 64 * PST)        // 55040
#define SM_TOT_BYTES  (SM_TOT_FLOATS * 4)       // 220160 (< 227KB opt-in max)

__global__ __launch_bounds__(256)
void block_attn(float* __restrict__ outO, float* __restrict__ outW)
{
    extern __shared__ float sm[];
    float* Qs = sm + SM_QS;
    float* Kt = sm + SM_KT;
    float* Vs = sm + SM_VS;
    float* Ps = sm + SM_PS;

    const int bs  = blockIdx.x;                    // b*S + s
    const int tid = threadIdx.x;
    const size_t gbase = (size_t)bs * (NBLK * DIM);

    // Stage the (b,s) slab: 64 rows x 256 of Q, K (transposed), V
    for (int idx = tid; idx < NBLK * DIM / 4; idx += 256) {
        int r  = idx >> 6;            // row 0..63
        int c4 = (idx & 63) * 4;      // col 0..252
        float4 q = *(const float4*)&g_Q[gbase + r * DIM + c4];
        float4 k = *(const float4*)&g_K[gbase + r * DIM + c4];
        float4 v = *(const float4*)&g_V[gbase + r * DIM + c4];
        *(float4*)&Qs[r * QST + c4] = q;
        Kt[(c4 + 0) * KTST + r] = k.x;
        Kt[(c4 + 1) * KTST + r] = k.y;
        Kt[(c4 + 2) * KTST + r] = k.z;
        Kt[(c4 + 3) * KTST + r] = k.w;
        *(float4*)&Vs[r * QST + c4] = v;
    }
    __syncthreads();

    const int b  = bs / SS;
    const int s0 = bs % SS;
    const int tn = tid >> 4, tm = tid & 15;        // scores: 4x4 tile at (tn*4, tm*4)
    const int rrow = tid >> 2, rq = tid & 3;       // softmax: row rrow, 16-col quad rq
    const int an = (tid >> 3) * 2, ad = (tid & 7) * 4;  // PV: rows an..an+1, cols ad..ad+3
    const float scale = 0.17677669529663687f;      // 1/sqrt(32)

    for (int h = 0; h < NH; h++) {
        const int hoff = h * DHD;

        // ---- scores: S[n][m] = sum_d Q[n][d] K[m][d] * scale ----
        float accS[4][4] = {};
        #pragma unroll
        for (int d = 0; d < DHD; d += 4) {
            float4 qv[4];
            #pragma unroll
            for (int i = 0; i < 4; i++)
                qv[i] = *(const float4*)&Qs[(tn * 4 + i) * QST + hoff + d];
            #pragma unroll
            for (int dd = 0; dd < 4; dd++) {
                float4 kv = *(const float4*)&Kt[(hoff + d + dd) * KTST + tm * 4];
                #pragma unroll
                for (int i = 0; i < 4; i++) {
                    float a = (dd == 0) ? qv[i].x : (dd == 1) ? qv[i].y
                              : (dd == 2) ? qv[i].z : qv[i].w;
                    accS[i][0] += a * kv.x;
                    accS[i][1] += a * kv.y;
                    accS[i][2] += a * kv.z;
                    accS[i][3] += a * kv.w;
                }
            }
        }
        #pragma unroll
        for (int i = 0; i < 4; i++) {
            *(float4*)&Ps[(tn * 4 + i) * PST + tm * 4] =
                make_float4(accS[i][0] * scale, accS[i][1] * scale,
                            accS[i][2] * scale, accS[i][3] * scale);
        }
        __syncthreads();

        // ---- softmax over m: 4 lanes per row, 16 cols each ----
        float ev[16];
        #pragma unroll
        for (int t = 0; t < 4; t++) {
            float4 pv = *(const float4*)&Ps[rrow * PST + rq * 16 + t * 4];
            ev[4 * t + 0] = pv.x; ev[4 * t + 1] = pv.y;
            ev[4 * t + 2] = pv.z; ev[4 * t + 3] = pv.w;
        }
        float mx = ev[0];
        #pragma unroll
        for (int t = 1; t < 16; t++) mx = fmaxf(mx, ev[t]);
        mx = fmaxf(mx, __shfl_xor_sync(0xffffffffu, mx, 1));
        mx = fmaxf(mx, __shfl_xor_sync(0xffffffffu, mx, 2));
        float ssum = 0.f;
        #pragma unroll
        for (int t = 0; t < 16; t++) { ev[t] = __expf(ev[t] - mx); ssum += ev[t]; }
        ssum += __shfl_xor_sync(0xffffffffu, ssum, 1);
        ssum += __shfl_xor_sync(0xffffffffu, ssum, 2);
        float inv = 1.0f / ssum;

        size_t wbase = ((((size_t)b * NH + h) * SS + s0) * NBLK + rrow) * NBLK + rq * 16;
        #pragma unroll
        for (int t = 0; t < 4; t++) {
            float4 pv = make_float4(ev[4 * t + 0] * inv, ev[4 * t + 1] * inv,
                                    ev[4 * t + 2] * inv, ev[4 * t + 3] * inv);
            *(float4*)&Ps[rrow * PST + rq * 16 + t * 4] = pv;
            *(float4*)&outW[wbase + t * 4] = pv;
        }
        __syncthreads();

        // ---- PV: out[n][d'] = sum_m P[n][m] V[m][hoff + d'] ----
        float accO[2][4] = {};
        #pragma unroll
        for (int m = 0; m < NBLK; m += 4) {
            float4 p0 = *(const float4*)&Ps[(an + 0) * PST + m];
            float4 p1 = *(const float4*)&Ps[(an + 1) * PST + m];
            #pragma unroll
            for (int mm = 0; mm < 4; mm++) {
                float4 vv = *(const float4*)&Vs[(m + mm) * QST + hoff + ad];
                float a0 = (mm == 0) ? p0.x : (mm == 1) ? p0.y : (mm == 2) ? p0.z : p0.w;
                float a1 = (mm == 0) ? p1.x : (mm == 1) ? p1.y : (mm == 2) ? p1.z : p1.w;
                accO[0][0] += a0 * vv.x; accO[0][1] += a0 * vv.y;
                accO[0][2] += a0 * vv.z; accO[0][3] += a0 * vv.w;
                accO[1][0] += a1 * vv.x; accO[1][1] += a1 * vv.y;
                accO[1][2] += a1 * vv.z; accO[1][3] += a1 * vv.w;
            }
        }
        size_t obase = gbase + (size_t)an * DIM + hoff + ad;
        *(float4*)&outO[obase]       = make_float4(accO[0][0], accO[0][1], accO[0][2], accO[0][3]);
        *(float4*)&outO[obase + DIM] = make_float4(accO[1][0], accO[1][1], accO[1][2], accO[1][3]);
        __syncthreads();   // protect Ps before next head overwrites it
    }
}

// ---------------------------------------------------------------------------
// kernel_launch: inputs in reference-signature order
//   [0]=query [1]=key [2]=value [3]=Wq [4]=bq [5]=Wk [6]=bk [7]=Wv [8]=bv
// d_out = attn_output (B,S,NB,D) followed by attn_weight (B,H,S,NB,NB)
// ---------------------------------------------------------------------------
extern "C" void kernel_launch(void* const* d_in, const int* in_sizes, int n_in,
                              void* d_out, int out_size)
{
    const float* query = (const float*)d_in[0];
    const float* key   = (const float*)d_in[1];
    const float* value = (const float*)d_in[2];
    const float* Wq    = (const float*)d_in[3];
    const float* bq    = (const float*)d_in[4];
    const float* Wk    = (const float*)d_in[5];
    const float* bk    = (const float*)d_in[6];
    const float* Wv    = (const float*)d_in[7];
    const float* bv    = (const float*)d_in[8];

    float* attn_out = (float*)d_out;
    float* attn_w   = (float*)d_out + (size_t)BB * SS * NBLK * DIM;  // +33554432

    dim3 gg(DIM / BN, NROWS / BM);   // (2, 1024)
    proj_gemm<<<gg, 256>>>(query, Wq, bq, 0);
    proj_gemm<<<gg, 256>>>(key,   Wk, bk, 1);
    proj_gemm<<<gg, 256>>>(value, Wv, bv, 2);

    cudaFuncSetAttribute(block_attn, cudaFuncAttributeMaxDynamicSharedMemorySize,
                         SM_TOT_BYTES);
    block_attn<<<BB * SS, 256, SM_TOT_BYTES>>>(attn_out, attn_w);
}

// round 5
// speedup vs baseline: 1.7116x; 1.7116x over previous
#include <cuda_runtime.h>
#include <cuda_bf16.h>
#include <cstdint>

// Problem constants (fixed by the dataset)
#define BB    2
#define SS    1024
#define NBLK  64
#define DIM   256
#define NH    8
#define DHD   32
#define NROWS (BB * SS * NBLK)   // 131072

// ---------------------------------------------------------------------------
// Scratch (allocation-free rule: __device__ globals).
// ---------------------------------------------------------------------------
__device__ float g_Q[NROWS * DIM];
__device__ float g_K[NROWS * DIM];
__device__ float g_V[NROWS * DIM];
__device__ __nv_bfloat16 g_Whi[DIM * DIM];
__device__ __nv_bfloat16 g_Wlo[DIM * DIM];

// ---------------------------------------------------------------------------
// Helpers
// ---------------------------------------------------------------------------
__device__ __forceinline__ uint32_t smem_u32(const void* p) {
    uint32_t a;
    asm("{ .reg .u64 t; cvta.to.shared.u64 t, %1; cvt.u32.u64 %0, t; }"
        : "=r"(a) : "l"(p));
    return a;
}
__device__ __forceinline__ void ldmx4(uint32_t* r, uint32_t addr) {
    asm volatile("ldmatrix.sync.aligned.m8n8.x4.shared.b16 {%0,%1,%2,%3}, [%4];"
                 : "=r"(r[0]), "=r"(r[1]), "=r"(r[2]), "=r"(r[3]) : "r"(addr));
}
__device__ __forceinline__ void mma16816(float* d, const uint32_t* a,
                                         uint32_t b0, uint32_t b1) {
    asm volatile("mma.sync.aligned.m16n8k16.row.col.f32.bf16.bf16.f32 "
                 "{%0,%1,%2,%3}, {%4,%5,%6,%7}, {%8,%9}, {%0,%1,%2,%3};"
                 : "+f"(d[0]), "+f"(d[1]), "+f"(d[2]), "+f"(d[3])
                 : "r"(a[0]), "r"(a[1]), "r"(a[2]), "r"(a[3]), "r"(b0), "r"(b1));
}
__device__ __forceinline__ void cpasync16(uint32_t saddr, const void* gptr) {
    asm volatile("cp.async.cg.shared.global [%0], [%1], 16;"
                 :: "r"(saddr), "l"(gptr) : "memory");
}
#define CP_COMMIT_WAIT() do {                                   \
    asm volatile("cp.async.commit_group;" ::: "memory");        \
    asm volatile("cp.async.wait_group 0;" ::: "memory");        \
} while (0)

// ---------------------------------------------------------------------------
// W pre-split: fp32 -> bf16 hi/lo
// ---------------------------------------------------------------------------
__global__ void convW(const float* __restrict__ W) {
    int i = blockIdx.x * 256 + threadIdx.x;
    float x = W[i];
    __nv_bfloat16 h = __float2bfloat16(x);
    g_Whi[i] = h;
    g_Wlo[i] = __float2bfloat16(x - __bfloat162float(h));
}

// fp32x8 -> bf16 hi/lo 16-byte packs
__device__ __forceinline__ void cvt8(float4 a, float4 b, uint4& hi, uint4& lo) {
    __nv_bfloat162 h0 = __float22bfloat162_rn(make_float2(a.x, a.y));
    __nv_bfloat162 h1 = __float22bfloat162_rn(make_float2(a.z, a.w));
    __nv_bfloat162 h2 = __float22bfloat162_rn(make_float2(b.x, b.y));
    __nv_bfloat162 h3 = __float22bfloat162_rn(make_float2(b.z, b.w));
    float2 f0 = __bfloat1622float2(h0), f1 = __bfloat1622float2(h1);
    float2 f2 = __bfloat1622float2(h2), f3 = __bfloat1622float2(h3);
    __nv_bfloat162 l0 = __float22bfloat162_rn(make_float2(a.x - f0.x, a.y - f0.y));
    __nv_bfloat162 l1 = __float22bfloat162_rn(make_float2(a.z - f1.x, a.w - f1.y));
    __nv_bfloat162 l2 = __float22bfloat162_rn(make_float2(b.x - f2.x, b.y - f2.y));
    __nv_bfloat162 l3 = __float22bfloat162_rn(make_float2(b.z - f3.x, b.w - f3.y));
    hi.x = *(uint32_t*)&h0; hi.y = *(uint32_t*)&h1;
    hi.z = *(uint32_t*)&h2; hi.w = *(uint32_t*)&h3;
    lo.x = *(uint32_t*)&l0; lo.y = *(uint32_t*)&l1;
    lo.z = *(uint32_t*)&l2; lo.w = *(uint32_t*)&l3;
}

// ---------------------------------------------------------------------------
// Projection GEMM on the tensor pipe via mma.sync (bf16 hi/lo split).
// C[n, j] = sum_k X[n, k] * W[j, k] + bias[j]
// CTA: 128 (M) x 128 (N), K=256 in 8 chunks of 32. 8 warps, warp tile 32x64.
// smem tiles padded to stride 40 b16 (80 B) -> conflict-free ldmatrix.
// ---------------------------------------------------------------------------
#define BK    32
#define TSTR  40                        // b16 stride per row
#define TILE_B16 (128 * TSTR)           // 5120 b16 = 10240 bytes per variant

__global__ __launch_bounds__(256)
void proj_mma(const float* __restrict__ X, const float* __restrict__ bias, int which)
{
    __shared__ __align__(16) __nv_bfloat16 Ah[TILE_B16];
    __shared__ __align__(16) __nv_bfloat16 Al[TILE_B16];
    __shared__ __align__(16) __nv_bfloat16 Bh[TILE_B16];
    __shared__ __align__(16) __nv_bfloat16 Bl[TILE_B16];

    float* C = (which == 0) ? g_Q : (which == 1) ? g_K : g_V;

    const int tid  = threadIdx.x;
    const int wid  = tid >> 5, lane = tid & 31;
    const int warpM = wid & 3, warpN = wid >> 2;       // 4 x 2 warp grid
    const int colBase = blockIdx.x * 128;
    const int rowBase = blockIdx.y * 128;

    const uint32_t sAh = smem_u32(Ah), sAl = smem_u32(Al);
    const uint32_t sBh = smem_u32(Bh), sBl = smem_u32(Bl);

    // ldmatrix lane addressing: rows = lane%16, k-half = lane/16
    const int lrow = lane & 15, lkh = (lane >> 4) * 8;

    float acc[2][8][4];
    #pragma unroll
    for (int i = 0; i < 2; i++)
        #pragma unroll
        for (int j = 0; j < 8; j++)
            #pragma unroll
            for (int q = 0; q < 4; q++) acc[i][j][q] = 0.f;

    // Staging index: 8 floats (2x float4) per thread-iter; 128 rows x 4 segs
    const int arow = tid >> 1, aseg = tid & 1;          // 2 iters cover seg 0..3

    for (int kc = 0; kc < DIM; kc += BK) {
        // B tiles: direct bf16 cp.async (2 x 16B per variant per thread)
        #pragma unroll
        for (int t = 0; t < 2; t++) {
            int idx = t * 256 + tid;                    // 0..511
            int n = idx >> 2, seg = idx & 3;            // 8 bf16 per seg
            uint32_t soff = (uint32_t)(n * TSTR + seg * 8) * 2;
            cpasync16(sBh + soff, g_Whi + (colBase + n) * DIM + kc + seg * 8);
            cpasync16(sBl + soff, g_Wlo + (colBase + n) * DIM + kc + seg * 8);
        }
        // A tile: fp32 load + convert to hi/lo
        #pragma unroll
        for (int t = 0; t < 2; t++) {
            int r = arow, seg = aseg + 2 * t;           // seg 0..3
            const float4* p = (const float4*)(X + (size_t)(rowBase + r) * DIM
                                              + kc + seg * 8);
            float4 a = p[0], b = p[1];
            uint4 hi, lo;
            cvt8(a, b, hi, lo);
            uint32_t soff = (uint32_t)(r * TSTR + seg * 8) * 2;
            *(uint4*)((char*)Ah + soff) = hi;
            *(uint4*)((char*)Al + soff) = lo;
        }
        CP_COMMIT_WAIT();
        __syncthreads();

        #pragma unroll
        for (int ks = 0; ks < 2; ks++) {                // two k16 steps per chunk
            const uint32_t kbyte = (uint32_t)(ks * 16 + lkh) * 2;
            // A fragments (hi & lo) for both m-tiles
            uint32_t ah[2][4], al[2][4];
            #pragma unroll
            for (int mt = 0; mt < 2; mt++) {
                uint32_t ro = (uint32_t)((warpM * 32 + mt * 16 + lrow) * TSTR) * 2;
                ldmx4(ah[mt], sAh + ro + kbyte);
                ldmx4(al[mt], sAl + ro + kbyte);
            }
            // B fragments per n16 pair, then MMAs
            #pragma unroll
            for (int p = 0; p < 4; p++) {
                uint32_t ro = (uint32_t)((warpN * 64 + p * 16 + lrow) * TSTR) * 2;
                uint32_t bh[4], bl[4];
                ldmx4(bh, sBh + ro + kbyte);
                ldmx4(bl, sBl + ro + kbyte);
                #pragma unroll
                for (int mt = 0; mt < 2; mt++) {
                    // n-tile 2p   uses {r0, r2}; n-tile 2p+1 uses {r1, r3}
                    mma16816(acc[mt][2 * p + 0], ah[mt], bh[0], bh[2]);
                    mma16816(acc[mt][2 * p + 0], ah[mt], bl[0], bl[2]);
                    mma16816(acc[mt][2 * p + 0], al[mt], bh[0], bh[2]);
                    mma16816(acc[mt][2 * p + 1], ah[mt], bh[1], bh[3]);
                    mma16816(acc[mt][2 * p + 1], ah[mt], bl[1], bl[3]);
                    mma16816(acc[mt][2 * p + 1], al[mt], bh[1], bh[3]);
                }
            }
        }
        __syncthreads();
    }

    // Epilogue: add bias, store fp32. Fragment map: row = lane/4 (+8), col = (lane%4)*2.
    const int crow0 = rowBase + warpM * 32 + (lane >> 2);
    const int ccol0 = colBase + warpN * 64 + (lane & 3) * 2;
    #pragma unroll
    for (int nt = 0; nt < 8; nt++) {
        int col = ccol0 + nt * 8;
        float b0 = bias[col], b1 = bias[col + 1];
        #pragma unroll
        for (int mt = 0; mt < 2; mt++) {
            float* d = acc[mt][nt];
            int r0 = crow0 + mt * 16;
            *(float2*)(C + (size_t)r0 * DIM + col)       = make_float2(d[0] + b0, d[1] + b1);
            *(float2*)(C + (size_t)(r0 + 8) * DIM + col) = make_float2(d[2] + b0, d[3] + b1);
        }
    }
}

// ---------------------------------------------------------------------------
// Block attention (unchanged): one CTA per (b, s).
// ---------------------------------------------------------------------------
#define QST  260
#define KTST 68
#define PST  68
#define SM_QS 0
#define SM_KT (64 * QST)
#define SM_VS (SM_KT + DIM * KTST)
#define SM_PS (SM_VS + 64 * QST)
#define SM_TOT_FLOATS (SM_PS + 64 * PST)
#define SM_TOT_BYTES  (SM_TOT_FLOATS * 4)   // 220160

__global__ __launch_bounds__(256)
void block_attn(float* __restrict__ outO, float* __restrict__ outW)
{
    extern __shared__ float sm[];
    float* Qs = sm + SM_QS;
    float* Kt = sm + SM_KT;
    float* Vs = sm + SM_VS;
    float* Ps = sm + SM_PS;

    const int bs  = blockIdx.x;
    const int tid = threadIdx.x;
    const size_t gbase = (size_t)bs * (NBLK * DIM);

    for (int idx = tid; idx < NBLK * DIM / 4; idx += 256) {
        int r  = idx >> 6;
        int c4 = (idx & 63) * 4;
        float4 q = *(const float4*)&g_Q[gbase + r * DIM + c4];
        float4 k = *(const float4*)&g_K[gbase + r * DIM + c4];
        float4 v = *(const float4*)&g_V[gbase + r * DIM + c4];
        *(float4*)&Qs[r * QST + c4] = q;
        Kt[(c4 + 0) * KTST + r] = k.x;
        Kt[(c4 + 1) * KTST + r] = k.y;
        Kt[(c4 + 2) * KTST + r] = k.z;
        Kt[(c4 + 3) * KTST + r] = k.w;
        *(float4*)&Vs[r * QST + c4] = v;
    }
    __syncthreads();

    const int b  = bs / SS;
    const int s0 = bs % SS;
    const int tn = tid >> 4, tm = tid & 15;
    const int rrow = tid >> 2, rq = tid & 3;
    const int an = (tid >> 3) * 2, ad = (tid & 7) * 4;
    const float scale = 0.17677669529663687f;

    for (int h = 0; h < NH; h++) {
        const int hoff = h * DHD;

        float accS[4][4] = {};
        #pragma unroll
        for (int d = 0; d < DHD; d += 4) {
            float4 qv[4];
            #pragma unroll
            for (int i = 0; i < 4; i++)
                qv[i] = *(const float4*)&Qs[(tn * 4 + i) * QST + hoff + d];
            #pragma unroll
            for (int dd = 0; dd < 4; dd++) {
                float4 kv = *(const float4*)&Kt[(hoff + d + dd) * KTST + tm * 4];
                #pragma unroll
                for (int i = 0; i < 4; i++) {
                    float a = (dd == 0) ? qv[i].x : (dd == 1) ? qv[i].y
                              : (dd == 2) ? qv[i].z : qv[i].w;
                    accS[i][0] += a * kv.x;
                    accS[i][1] += a * kv.y;
                    accS[i][2] += a * kv.z;
                    accS[i][3] += a * kv.w;
                }
            }
        }
        #pragma unroll
        for (int i = 0; i < 4; i++) {
            *(float4*)&Ps[(tn * 4 + i) * PST + tm * 4] =
                make_float4(accS[i][0] * scale, accS[i][1] * scale,
                            accS[i][2] * scale, accS[i][3] * scale);
        }
        __syncthreads();

        float ev[16];
        #pragma unroll
        for (int t = 0; t < 4; t++) {
            float4 pv = *(const float4*)&Ps[rrow * PST + rq * 16 + t * 4];
            ev[4 * t + 0] = pv.x; ev[4 * t + 1] = pv.y;
            ev[4 * t + 2] = pv.z; ev[4 * t + 3] = pv.w;
        }
        float mx = ev[0];
        #pragma unroll
        for (int t = 1; t < 16; t++) mx = fmaxf(mx, ev[t]);
        mx = fmaxf(mx, __shfl_xor_sync(0xffffffffu, mx, 1));
        mx = fmaxf(mx, __shfl_xor_sync(0xffffffffu, mx, 2));
        float ssum = 0.f;
        #pragma unroll
        for (int t = 0; t < 16; t++) { ev[t] = __expf(ev[t] - mx); ssum += ev[t]; }
        ssum += __shfl_xor_sync(0xffffffffu, ssum, 1);
        ssum += __shfl_xor_sync(0xffffffffu, ssum, 2);
        float inv = 1.0f / ssum;

        size_t wbase = ((((size_t)b * NH + h) * SS + s0) * NBLK + rrow) * NBLK + rq * 16;
        #pragma unroll
        for (int t = 0; t < 4; t++) {
            float4 pv = make_float4(ev[4 * t + 0] * inv, ev[4 * t + 1] * inv,
                                    ev[4 * t + 2] * inv, ev[4 * t + 3] * inv);
            *(float4*)&Ps[rrow * PST + rq * 16 + t * 4] = pv;
            *(float4*)&outW[wbase + t * 4] = pv;
        }
        __syncthreads();

        float accO[2][4] = {};
        #pragma unroll
        for (int m = 0; m < NBLK; m += 4) {
            float4 p0 = *(const float4*)&Ps[(an + 0) * PST + m];
            float4 p1 = *(const float4*)&Ps[(an + 1) * PST + m];
            #pragma unroll
            for (int mm = 0; mm < 4; mm++) {
                float4 vv = *(const float4*)&Vs[(m + mm) * QST + hoff + ad];
                float a0 = (mm == 0) ? p0.x : (mm == 1) ? p0.y : (mm == 2) ? p0.z : p0.w;
                float a1 = (mm == 0) ? p1.x : (mm == 1) ? p1.y : (mm == 2) ? p1.z : p1.w;
                accO[0][0] += a0 * vv.x; accO[0][1] += a0 * vv.y;
                accO[0][2] += a0 * vv.z; accO[0][3] += a0 * vv.w;
                accO[1][0] += a1 * vv.x; accO[1][1] += a1 * vv.y;
                accO[1][2] += a1 * vv.z; accO[1][3] += a1 * vv.w;
            }
        }
        size_t obase = gbase + (size_t)an * DIM + hoff + ad;
        *(float4*)&outO[obase]       = make_float4(accO[0][0], accO[0][1], accO[0][2], accO[0][3]);
        *(float4*)&outO[obase + DIM] = make_float4(accO[1][0], accO[1][1], accO[1][2], accO[1][3]);
        __syncthreads();
    }
}

// ---------------------------------------------------------------------------
// kernel_launch
// ---------------------------------------------------------------------------
extern "C" void kernel_launch(void* const* d_in, const int* in_sizes, int n_in,
                              void* d_out, int out_size)
{
    const float* query = (const float*)d_in[0];
    const float* key   = (const float*)d_in[1];
    const float* value = (const float*)d_in[2];
    const float* Wq    = (const float*)d_in[3];
    const float* bq    = (const float*)d_in[4];
    const float* Wk    = (const float*)d_in[5];
    const float* bk    = (const float*)d_in[6];
    const float* Wv    = (const float*)d_in[7];
    const float* bv    = (const float*)d_in[8];

    float* attn_out = (float*)d_out;
    float* attn_w   = (float*)d_out + (size_t)BB * SS * NBLK * DIM;

    cudaFuncSetAttribute(block_attn, cudaFuncAttributeMaxDynamicSharedMemorySize,
                         SM_TOT_BYTES);

    dim3 gg(DIM / 128, NROWS / 128);   // (2, 1024)
    convW<<<256, 256>>>(Wq);
    proj_mma<<<gg, 256>>>(query, bq, 0);
    convW<<<256, 256>>>(Wk);
    proj_mma<<<gg, 256>>>(key, bk, 1);
    convW<<<256, 256>>>(Wv);
    proj_mma<<<gg, 256>>>(value, bv, 2);

    block_attn<<<BB * SS, 256, SM_TOT_BYTES>>>(attn_out, attn_w);
}

// round 6
// speedup vs baseline: 1.7145x; 1.0017x over previous
#include <cuda_runtime.h>
#include <cuda_bf16.h>
#include <cstdint>

// Problem constants (fixed by the dataset)
#define BB    2
#define SS    1024
#define NBLK  64
#define DIM   256
#define NH    8
#define DHD   32
#define NROWS (BB * SS * NBLK)   // 131072

// ---------------------------------------------------------------------------
// Scratch (allocation-free rule: __device__ globals).
// ---------------------------------------------------------------------------
__device__ float g_Q[NROWS * DIM];
__device__ float g_K[NROWS * DIM];
__device__ float g_V[NROWS * DIM];
__device__ __nv_bfloat16 g_Whi[DIM * DIM];
__device__ __nv_bfloat16 g_Wlo[DIM * DIM];

// ---------------------------------------------------------------------------
// Helpers
// ---------------------------------------------------------------------------
__device__ __forceinline__ uint32_t smem_u32(const void* p) {
    uint32_t a;
    asm("{ .reg .u64 t; cvta.to.shared.u64 t, %1; cvt.u32.u64 %0, t; }"
        : "=r"(a) : "l"(p));
    return a;
}
__device__ __forceinline__ void ldmx4(uint32_t* r, uint32_t addr) {
    asm volatile("ldmatrix.sync.aligned.m8n8.x4.shared.b16 {%0,%1,%2,%3}, [%4];"
                 : "=r"(r[0]), "=r"(r[1]), "=r"(r[2]), "=r"(r[3]) : "r"(addr));
}
__device__ __forceinline__ void mma16816(float* d, const uint32_t* a,
                                         uint32_t b0, uint32_t b1) {
    asm volatile("mma.sync.aligned.m16n8k16.row.col.f32.bf16.bf16.f32 "
                 "{%0,%1,%2,%3}, {%4,%5,%6,%7}, {%8,%9}, {%0,%1,%2,%3};"
                 : "+f"(d[0]), "+f"(d[1]), "+f"(d[2]), "+f"(d[3])
                 : "r"(a[0]), "r"(a[1]), "r"(a[2]), "r"(a[3]), "r"(b0), "r"(b1));
}
__device__ __forceinline__ void cpasync16(uint32_t saddr, const void* gptr) {
    asm volatile("cp.async.cg.shared.global [%0], [%1], 16;"
                 :: "r"(saddr), "l"(gptr) : "memory");
}
#define CP_COMMIT_WAIT() do {                                   \
    asm volatile("cp.async.commit_group;" ::: "memory");        \
    asm volatile("cp.async.wait_group 0;" ::: "memory");        \
} while (0)

// ---------------------------------------------------------------------------
// W pre-split: fp32 -> bf16 hi/lo
// ---------------------------------------------------------------------------
__global__ void convW(const float* __restrict__ W) {
    int i = blockIdx.x * 256 + threadIdx.x;
    float x = W[i];
    __nv_bfloat16 h = __float2bfloat16(x);
    g_Whi[i] = h;
    g_Wlo[i] = __float2bfloat16(x - __bfloat162float(h));
}

// fp32x8 -> bf16 hi/lo 16-byte packs
__device__ __forceinline__ void cvt8(float4 a, float4 b, uint4& hi, uint4& lo) {
    __nv_bfloat162 h0 = __float22bfloat162_rn(make_float2(a.x, a.y));
    __nv_bfloat162 h1 = __float22bfloat162_rn(make_float2(a.z, a.w));
    __nv_bfloat162 h2 = __float22bfloat162_rn(make_float2(b.x, b.y));
    __nv_bfloat162 h3 = __float22bfloat162_rn(make_float2(b.z, b.w));
    float2 f0 = __bfloat1622float2(h0), f1 = __bfloat1622float2(h1);
    float2 f2 = __bfloat1622float2(h2), f3 = __bfloat1622float2(h3);
    __nv_bfloat162 l0 = __float22bfloat162_rn(make_float2(a.x - f0.x, a.y - f0.y));
    __nv_bfloat162 l1 = __float22bfloat162_rn(make_float2(a.z - f1.x, a.w - f1.y));
    __nv_bfloat162 l2 = __float22bfloat162_rn(make_float2(b.x - f2.x, b.y - f2.y));
    __nv_bfloat162 l3 = __float22bfloat162_rn(make_float2(b.z - f3.x, b.w - f3.y));
    hi.x = *(uint32_t*)&h0; hi.y = *(uint32_t*)&h1;
    hi.z = *(uint32_t*)&h2; hi.w = *(uint32_t*)&h3;
    lo.x = *(uint32_t*)&l0; lo.y = *(uint32_t*)&l1;
    lo.z = *(uint32_t*)&l2; lo.w = *(uint32_t*)&l3;
}

// ---------------------------------------------------------------------------
// Projection GEMM on the tensor pipe via mma.sync (bf16 hi/lo split).
// C[n, j] = sum_k X[n, k] * W[j, k] + bias[j]
// CTA: 128 (M) x 128 (N), K=256 in 8 chunks of 32. 8 warps, warp tile 32x64.
// smem tiles padded to stride 40 b16 (80 B) -> conflict-free ldmatrix.
// ---------------------------------------------------------------------------
#define BK    32
#define TSTR  40                        // b16 stride per row
#define TILE_B16 (128 * TSTR)           // 5120 b16 = 10240 bytes per variant

__global__ __launch_bounds__(256)
void proj_mma(const float* __restrict__ X, const float* __restrict__ bias, int which)
{
    __shared__ __align__(16) __nv_bfloat16 Ah[TILE_B16];
    __shared__ __align__(16) __nv_bfloat16 Al[TILE_B16];
    __shared__ __align__(16) __nv_bfloat16 Bh[TILE_B16];
    __shared__ __align__(16) __nv_bfloat16 Bl[TILE_B16];

    float* C = (which == 0) ? g_Q : (which == 1) ? g_K : g_V;

    const int tid  = threadIdx.x;
    const int wid  = tid >> 5, lane = tid & 31;
    const int warpM = wid & 3, warpN = wid >> 2;       // 4 x 2 warp grid
    const int colBase = blockIdx.x * 128;
    const int rowBase = blockIdx.y * 128;

    const uint32_t sAh = smem_u32(Ah), sAl = smem_u32(Al);
    const uint32_t sBh = smem_u32(Bh), sBl = smem_u32(Bl);

    // ldmatrix lane addressing: rows = lane%16, k-half = lane/16
    const int lrow = lane & 15, lkh = (lane >> 4) * 8;

    float acc[2][8][4];
    #pragma unroll
    for (int i = 0; i < 2; i++)
        #pragma unroll
        for (int j = 0; j < 8; j++)
            #pragma unroll
            for (int q = 0; q < 4; q++) acc[i][j][q] = 0.f;

    // Staging index: 8 floats (2x float4) per thread-iter; 128 rows x 4 segs
    const int arow = tid >> 1, aseg = tid & 1;          // 2 iters cover seg 0..3

    for (int kc = 0; kc < DIM; kc += BK) {
        // B tiles: direct bf16 cp.async (2 x 16B per variant per thread)
        #pragma unroll
        for (int t = 0; t < 2; t++) {
            int idx = t * 256 + tid;                    // 0..511
            int n = idx >> 2, seg = idx & 3;            // 8 bf16 per seg
            uint32_t soff = (uint32_t)(n * TSTR + seg * 8) * 2;
            cpasync16(sBh + soff, g_Whi + (colBase + n) * DIM + kc + seg * 8);
            cpasync16(sBl + soff, g_Wlo + (colBase + n) * DIM + kc + seg * 8);
        }
        // A tile: fp32 load + convert to hi/lo
        #pragma unroll
        for (int t = 0; t < 2; t++) {
            int r = arow, seg = aseg + 2 * t;           // seg 0..3
            const float4* p = (const float4*)(X + (size_t)(rowBase + r) * DIM
                                              + kc + seg * 8);
            float4 a = p[0], b = p[1];
            uint4 hi, lo;
            cvt8(a, b, hi, lo);
            uint32_t soff = (uint32_t)(r * TSTR + seg * 8) * 2;
            *(uint4*)((char*)Ah + soff) = hi;
            *(uint4*)((char*)Al + soff) = lo;
        }
        CP_COMMIT_WAIT();
        __syncthreads();

        #pragma unroll
        for (int ks = 0; ks < 2; ks++) {                // two k16 steps per chunk
            const uint32_t kbyte = (uint32_t)(ks * 16 + lkh) * 2;
            // A fragments (hi & lo) for both m-tiles
            uint32_t ah[2][4], al[2][4];
            #pragma unroll
            for (int mt = 0; mt < 2; mt++) {
                uint32_t ro = (uint32_t)((warpM * 32 + mt * 16 + lrow) * TSTR) * 2;
                ldmx4(ah[mt], sAh + ro + kbyte);
                ldmx4(al[mt], sAl + ro + kbyte);
            }
            // B fragments per n16 pair, then MMAs
            #pragma unroll
            for (int p = 0; p < 4; p++) {
                uint32_t ro = (uint32_t)((warpN * 64 + p * 16 + lrow) * TSTR) * 2;
                uint32_t bh[4], bl[4];
                ldmx4(bh, sBh + ro + kbyte);
                ldmx4(bl, sBl + ro + kbyte);
                #pragma unroll
                for (int mt = 0; mt < 2; mt++) {
                    // n-tile 2p   uses {r0, r2}; n-tile 2p+1 uses {r1, r3}
                    mma16816(acc[mt][2 * p + 0], ah[mt], bh[0], bh[2]);
                    mma16816(acc[mt][2 * p + 0], ah[mt], bl[0], bl[2]);
                    mma16816(acc[mt][2 * p + 0], al[mt], bh[0], bh[2]);
                    mma16816(acc[mt][2 * p + 1], ah[mt], bh[1], bh[3]);
                    mma16816(acc[mt][2 * p + 1], ah[mt], bl[1], bl[3]);
                    mma16816(acc[mt][2 * p + 1], al[mt], bh[1], bh[3]);
                }
            }
        }
        __syncthreads();
    }

    // Epilogue: add bias, store fp32. Fragment map: row = lane/4 (+8), col = (lane%4)*2.
    const int crow0 = rowBase + warpM * 32 + (lane >> 2);
    const int ccol0 = colBase + warpN * 64 + (lane & 3) * 2;
    #pragma unroll
    for (int nt = 0; nt < 8; nt++) {
        int col = ccol0 + nt * 8;
        float b0 = bias[col], b1 = bias[col + 1];
        #pragma unroll
        for (int mt = 0; mt < 2; mt++) {
            float* d = acc[mt][nt];
            int r0 = crow0 + mt * 16;
            *(float2*)(C + (size_t)r0 * DIM + col)       = make_float2(d[0] + b0, d[1] + b1);
            *(float2*)(C + (size_t)(r0 + 8) * DIM + col) = make_float2(d[2] + b0, d[3] + b1);
        }
    }
}

// ---------------------------------------------------------------------------
// Block attention (unchanged): one CTA per (b, s).
// ---------------------------------------------------------------------------
#define QST  260
#define KTST 68
#define PST  68
#define SM_QS 0
#define SM_KT (64 * QST)
#define SM_VS (SM_KT + DIM * KTST)
#define SM_PS (SM_VS + 64 * QST)
#define SM_TOT_FLOATS (SM_PS + 64 * PST)
#define SM_TOT_BYTES  (SM_TOT_FLOATS * 4)   // 220160

__global__ __launch_bounds__(256)
void block_attn(float* __restrict__ outO, float* __restrict__ outW)
{
    extern __shared__ float sm[];
    float* Qs = sm + SM_QS;
    float* Kt = sm + SM_KT;
    float* Vs = sm + SM_VS;
    float* Ps = sm + SM_PS;

    const int bs  = blockIdx.x;
    const int tid = threadIdx.x;
    const size_t gbase = (size_t)bs * (NBLK * DIM);

    for (int idx = tid; idx < NBLK * DIM / 4; idx += 256) {
        int r  = idx >> 6;
        int c4 = (idx & 63) * 4;
        float4 q = *(const float4*)&g_Q[gbase + r * DIM + c4];
        float4 k = *(const float4*)&g_K[gbase + r * DIM + c4];
        float4 v = *(const float4*)&g_V[gbase + r * DIM + c4];
        *(float4*)&Qs[r * QST + c4] = q;
        Kt[(c4 + 0) * KTST + r] = k.x;
        Kt[(c4 + 1) * KTST + r] = k.y;
        Kt[(c4 + 2) * KTST + r] = k.z;
        Kt[(c4 + 3) * KTST + r] = k.w;
        *(float4*)&Vs[r * QST + c4] = v;
    }
    __syncthreads();

    const int b  = bs / SS;
    const int s0 = bs % SS;
    const int tn = tid >> 4, tm = tid & 15;
    const int rrow = tid >> 2, rq = tid & 3;
    const int an = (tid >> 3) * 2, ad = (tid & 7) * 4;
    const float scale = 0.17677669529663687f;

    for (int h = 0; h < NH; h++) {
        const int hoff = h * DHD;

        float accS[4][4] = {};
        #pragma unroll
        for (int d = 0; d < DHD; d += 4) {
            float4 qv[4];
            #pragma unroll
            for (int i = 0; i < 4; i++)
                qv[i] = *(const float4*)&Qs[(tn * 4 + i) * QST + hoff + d];
            #pragma unroll
            for (int dd = 0; dd < 4; dd++) {
                float4 kv = *(const float4*)&Kt[(hoff + d + dd) * KTST + tm * 4];
                #pragma unroll
                for (int i = 0; i < 4; i++) {
                    float a = (dd == 0) ? qv[i].x : (dd == 1) ? qv[i].y
                              : (dd == 2) ? qv[i].z : qv[i].w;
                    accS[i][0] += a * kv.x;
                    accS[i][1] += a * kv.y;
                    accS[i][2] += a * kv.z;
                    accS[i][3] += a * kv.w;
                }
            }
        }
        #pragma unroll
        for (int i = 0; i < 4; i++) {
            *(float4*)&Ps[(tn * 4 + i) * PST + tm * 4] =
                make_float4(accS[i][0] * scale, accS[i][1] * scale,
                            accS[i][2] * scale, accS[i][3] * scale);
        }
        __syncthreads();

        float ev[16];
        #pragma unroll
        for (int t = 0; t < 4; t++) {
            float4 pv = *(const float4*)&Ps[rrow * PST + rq * 16 + t * 4];
            ev[4 * t + 0] = pv.x; ev[4 * t + 1] = pv.y;
            ev[4 * t + 2] = pv.z; ev[4 * t + 3] = pv.w;
        }
        float mx = ev[0];
        #pragma unroll
        for (int t = 1; t < 16; t++) mx = fmaxf(mx, ev[t]);
        mx = fmaxf(mx, __shfl_xor_sync(0xffffffffu, mx, 1));
        mx = fmaxf(mx, __shfl_xor_sync(0xffffffffu, mx, 2));
        float ssum = 0.f;
        #pragma unroll
        for (int t = 0; t < 16; t++) { ev[t] = __expf(ev[t] - mx); ssum += ev[t]; }
        ssum += __shfl_xor_sync(0xffffffffu, ssum, 1);
        ssum += __shfl_xor_sync(0xffffffffu, ssum, 2);
        float inv = 1.0f / ssum;

        size_t wbase = ((((size_t)b * NH + h) * SS + s0) * NBLK + rrow) * NBLK + rq * 16;
        #pragma unroll
        for (int t = 0; t < 4; t++) {
            float4 pv = make_float4(ev[4 * t + 0] * inv, ev[4 * t + 1] * inv,
                                    ev[4 * t + 2] * inv, ev[4 * t + 3] * inv);
            *(float4*)&Ps[rrow * PST + rq * 16 + t * 4] = pv;
            *(float4*)&outW[wbase + t * 4] = pv;
        }
        __syncthreads();

        float accO[2][4] = {};
        #pragma unroll
        for (int m = 0; m < NBLK; m += 4) {
            float4 p0 = *(const float4*)&Ps[(an + 0) * PST + m];
            float4 p1 = *(const float4*)&Ps[(an + 1) * PST + m];
            #pragma unroll
            for (int mm = 0; mm < 4; mm++) {
                float4 vv = *(const float4*)&Vs[(m + mm) * QST + hoff + ad];
                float a0 = (mm == 0) ? p0.x : (mm == 1) ? p0.y : (mm == 2) ? p0.z : p0.w;
                float a1 = (mm == 0) ? p1.x : (mm == 1) ? p1.y : (mm == 2) ? p1.z : p1.w;
                accO[0][0] += a0 * vv.x; accO[0][1] += a0 * vv.y;
                accO[0][2] += a0 * vv.z; accO[0][3] += a0 * vv.w;
                accO[1][0] += a1 * vv.x; accO[1][1] += a1 * vv.y;
                accO[1][2] += a1 * vv.z; accO[1][3] += a1 * vv.w;
            }
        }
        size_t obase = gbase + (size_t)an * DIM + hoff + ad;
        *(float4*)&outO[obase]       = make_float4(accO[0][0], accO[0][1], accO[0][2], accO[0][3]);
        *(float4*)&outO[obase + DIM] = make_float4(accO[1][0], accO[1][1], accO[1][2], accO[1][3]);
        __syncthreads();
    }
}

// ---------------------------------------------------------------------------
// kernel_launch
// ---------------------------------------------------------------------------
extern "C" void kernel_launch(void* const* d_in, const int* in_sizes, int n_in,
                              void* d_out, int out_size)
{
    const float* query = (const float*)d_in[0];
    const float* key   = (const float*)d_in[1];
    const float* value = (const float*)d_in[2];
    const float* Wq    = (const float*)d_in[3];
    const float* bq    = (const float*)d_in[4];
    const float* Wk    = (const float*)d_in[5];
    const float* bk    = (const float*)d_in[6];
    const float* Wv    = (const float*)d_in[7];
    const float* bv    = (const float*)d_in[8];

    float* attn_out = (float*)d_out;
    float* attn_w   = (float*)d_out + (size_t)BB * SS * NBLK * DIM;

    cudaFuncSetAttribute(block_attn, cudaFuncAttributeMaxDynamicSharedMemorySize,
                         SM_TOT_BYTES);

    dim3 gg(DIM / 128, NROWS / 128);   // (2, 1024)
    convW<<<256, 256>>>(Wq);
    proj_mma<<<gg, 256>>>(query, bq, 0);
    convW<<<256, 256>>>(Wk);
    proj_mma<<<gg, 256>>>(key, bk, 1);
    convW<<<256, 256>>>(Wv);
    proj_mma<<<gg, 256>>>(value, bv, 2);

    block_attn<<<BB * SS, 256, SM_TOT_BYTES>>>(attn_out, attn_w);
}

// round 7
// speedup vs baseline: 2.3989x; 1.3991x over previous
#include <cuda_runtime.h>
#include <cuda_bf16.h>
#include <cstdint>

// Problem constants (fixed by the dataset)
#define BB    2
#define SS    1024
#define NBLK  64
#define DIM   256
#define NH    8
#define DHD   32
#define NROWS (BB * SS * NBLK)   // 131072

// ---------------------------------------------------------------------------
// Scratch (allocation-free rule: __device__ globals).
// Projected Q/K/V stored as bf16 hi/lo pairs (exact to ~2^-17 combined).
// ---------------------------------------------------------------------------
__device__ __nv_bfloat16 g_Qh[NROWS * DIM];
__device__ __nv_bfloat16 g_Ql[NROWS * DIM];
__device__ __nv_bfloat16 g_Kh[NROWS * DIM];
__device__ __nv_bfloat16 g_Kl[NROWS * DIM];
__device__ __nv_bfloat16 g_Vh[NROWS * DIM];
__device__ __nv_bfloat16 g_Vl[NROWS * DIM];
__device__ __nv_bfloat16 g_Whi[DIM * DIM];
__device__ __nv_bfloat16 g_Wlo[DIM * DIM];

// ---------------------------------------------------------------------------
// Helpers
// ---------------------------------------------------------------------------
__device__ __forceinline__ uint32_t smem_u32(const void* p) {
    uint32_t a;
    asm("{ .reg .u64 t; cvta.to.shared.u64 t, %1; cvt.u32.u64 %0, t; }"
        : "=r"(a) : "l"(p));
    return a;
}
__device__ __forceinline__ void ldmx4(uint32_t* r, uint32_t addr) {
    asm volatile("ldmatrix.sync.aligned.m8n8.x4.shared.b16 {%0,%1,%2,%3}, [%4];"
                 : "=r"(r[0]), "=r"(r[1]), "=r"(r[2]), "=r"(r[3]) : "r"(addr));
}
__device__ __forceinline__ void ldmx4t(uint32_t* r, uint32_t addr) {
    asm volatile("ldmatrix.sync.aligned.m8n8.x4.trans.shared.b16 {%0,%1,%2,%3}, [%4];"
                 : "=r"(r[0]), "=r"(r[1]), "=r"(r[2]), "=r"(r[3]) : "r"(addr));
}
__device__ __forceinline__ void mma16816(float* d, const uint32_t* a,
                                         uint32_t b0, uint32_t b1) {
    asm volatile("mma.sync.aligned.m16n8k16.row.col.f32.bf16.bf16.f32 "
                 "{%0,%1,%2,%3}, {%4,%5,%6,%7}, {%8,%9}, {%0,%1,%2,%3};"
                 : "+f"(d[0]), "+f"(d[1]), "+f"(d[2]), "+f"(d[3])
                 : "r"(a[0]), "r"(a[1]), "r"(a[2]), "r"(a[3]), "r"(b0), "r"(b1));
}
__device__ __forceinline__ void cpasync16(uint32_t saddr, const void* gptr) {
    asm volatile("cp.async.cg.shared.global [%0], [%1], 16;"
                 :: "r"(saddr), "l"(gptr) : "memory");
}
#define CP_COMMIT_WAIT() do {                                   \
    asm volatile("cp.async.commit_group;" ::: "memory");        \
    asm volatile("cp.async.wait_group 0;" ::: "memory");        \
} while (0)

// fp32 pair -> bf16x2 hi + bf16x2 lo (residue)
__device__ __forceinline__ void hilo2(float x, float y, uint32_t& h, uint32_t& l) {
    __nv_bfloat162 hb = __float22bfloat162_rn(make_float2(x, y));
    float2 f = __bfloat1622float2(hb);
    __nv_bfloat162 lb = __float22bfloat162_rn(make_float2(x - f.x, y - f.y));
    h = *(uint32_t*)&hb;
    l = *(uint32_t*)&lb;
}

// ---------------------------------------------------------------------------
// W pre-split: fp32 -> bf16 hi/lo
// ---------------------------------------------------------------------------
__global__ void convW(const float* __restrict__ W) {
    int i = blockIdx.x * 256 + threadIdx.x;
    float x = W[i];
    __nv_bfloat16 h = __float2bfloat16(x);
    g_Whi[i] = h;
    g_Wlo[i] = __float2bfloat16(x - __bfloat162float(h));
}

// fp32x8 -> bf16 hi/lo 16-byte packs
__device__ __forceinline__ void cvt8(float4 a, float4 b, uint4& hi, uint4& lo) {
    uint32_t h0, h1, h2, h3, l0, l1, l2, l3;
    hilo2(a.x, a.y, h0, l0);
    hilo2(a.z, a.w, h1, l1);
    hilo2(b.x, b.y, h2, l2);
    hilo2(b.z, b.w, h3, l3);
    hi.x = h0; hi.y = h1; hi.z = h2; hi.w = h3;
    lo.x = l0; lo.y = l1; lo.z = l2; lo.w = l3;
}

// ---------------------------------------------------------------------------
// Projection GEMM on the tensor pipe via mma.sync (bf16 hi/lo split).
// C[n, j] = sum_k X[n, k] * W[j, k] + bias[j]; C emitted as bf16 hi/lo.
// CTA: 128 (M) x 128 (N), K=256 in 8 chunks of 32. 8 warps, warp tile 32x64.
// ---------------------------------------------------------------------------
#define BK    32
#define TSTR  40                        // b16 stride per row
#define TILE_B16 (128 * TSTR)

__global__ __launch_bounds__(256)
void proj_mma(const float* __restrict__ X, const float* __restrict__ bias, int which)
{
    __shared__ __align__(16) __nv_bfloat16 Ah[TILE_B16];
    __shared__ __align__(16) __nv_bfloat16 Al[TILE_B16];
    __shared__ __align__(16) __nv_bfloat16 Bh[TILE_B16];
    __shared__ __align__(16) __nv_bfloat16 Bl[TILE_B16];

    __nv_bfloat16* Ch = (which == 0) ? g_Qh : (which == 1) ? g_Kh : g_Vh;
    __nv_bfloat16* Cl = (which == 0) ? g_Ql : (which == 1) ? g_Kl : g_Vl;

    const int tid  = threadIdx.x;
    const int wid  = tid >> 5, lane = tid & 31;
    const int warpM = wid & 3, warpN = wid >> 2;       // 4 x 2 warp grid
    const int colBase = blockIdx.x * 128;
    const int rowBase = blockIdx.y * 128;

    const uint32_t sAh = smem_u32(Ah), sAl = smem_u32(Al);
    const uint32_t sBh = smem_u32(Bh), sBl = smem_u32(Bl);

    const int lrow = lane & 15, lkh = (lane >> 4) * 8;

    float acc[2][8][4];
    #pragma unroll
    for (int i = 0; i < 2; i++)
        #pragma unroll
        for (int j = 0; j < 8; j++)
            #pragma unroll
            for (int q = 0; q < 4; q++) acc[i][j][q] = 0.f;

    const int arow = tid >> 1, aseg = tid & 1;

    for (int kc = 0; kc < DIM; kc += BK) {
        #pragma unroll
        for (int t = 0; t < 2; t++) {
            int idx = t * 256 + tid;
            int n = idx >> 2, seg = idx & 3;
            uint32_t soff = (uint32_t)(n * TSTR + seg * 8) * 2;
            cpasync16(sBh + soff, g_Whi + (colBase + n) * DIM + kc + seg * 8);
            cpasync16(sBl + soff, g_Wlo + (colBase + n) * DIM + kc + seg * 8);
        }
        #pragma unroll
        for (int t = 0; t < 2; t++) {
            int r = arow, seg = aseg + 2 * t;
            const float4* p = (const float4*)(X + (size_t)(rowBase + r) * DIM
                                              + kc + seg * 8);
            float4 a = p[0], b = p[1];
            uint4 hi, lo;
            cvt8(a, b, hi, lo);
            uint32_t soff = (uint32_t)(r * TSTR + seg * 8) * 2;
            *(uint4*)((char*)Ah + soff) = hi;
            *(uint4*)((char*)Al + soff) = lo;
        }
        CP_COMMIT_WAIT();
        __syncthreads();

        #pragma unroll
        for (int ks = 0; ks < 2; ks++) {
            const uint32_t kbyte = (uint32_t)(ks * 16 + lkh) * 2;
            uint32_t ah[2][4], al[2][4];
            #pragma unroll
            for (int mt = 0; mt < 2; mt++) {
                uint32_t ro = (uint32_t)((warpM * 32 + mt * 16 + lrow) * TSTR) * 2;
                ldmx4(ah[mt], sAh + ro + kbyte);
                ldmx4(al[mt], sAl + ro + kbyte);
            }
            #pragma unroll
            for (int p = 0; p < 4; p++) {
                uint32_t ro = (uint32_t)((warpN * 64 + p * 16 + lrow) * TSTR) * 2;
                uint32_t bh[4], bl[4];
                ldmx4(bh, sBh + ro + kbyte);
                ldmx4(bl, sBl + ro + kbyte);
                #pragma unroll
                for (int mt = 0; mt < 2; mt++) {
                    mma16816(acc[mt][2 * p + 0], ah[mt], bh[0], bh[2]);
                    mma16816(acc[mt][2 * p + 0], ah[mt], bl[0], bl[2]);
                    mma16816(acc[mt][2 * p + 0], al[mt], bh[0], bh[2]);
                    mma16816(acc[mt][2 * p + 1], ah[mt], bh[1], bh[3]);
                    mma16816(acc[mt][2 * p + 1], ah[mt], bl[1], bl[3]);
                    mma16816(acc[mt][2 * p + 1], al[mt], bh[1], bh[3]);
                }
            }
        }
        __syncthreads();
    }

    // Epilogue: + bias, split to bf16 hi/lo, store as u32 (bf16x2) pairs
    const int crow0 = rowBase + warpM * 32 + (lane >> 2);
    const int ccol0 = colBase + warpN * 64 + (lane & 3) * 2;
    #pragma unroll
    for (int nt = 0; nt < 8; nt++) {
        int col = ccol0 + nt * 8;
        float b0 = bias[col], b1 = bias[col + 1];
        #pragma unroll
        for (int mt = 0; mt < 2; mt++) {
            float* d = acc[mt][nt];
            size_t r0 = (size_t)(crow0 + mt * 16) * DIM + col;
            uint32_t h, l;
            hilo2(d[0] + b0, d[1] + b1, h, l);
            *(uint32_t*)&Ch[r0] = h;
            *(uint32_t*)&Cl[r0] = l;
            hilo2(d[2] + b0, d[3] + b1, h, l);
            *(uint32_t*)&Ch[r0 + 8 * DIM] = h;
            *(uint32_t*)&Cl[r0 + 8 * DIM] = l;
        }
    }
}

// ---------------------------------------------------------------------------
// Tensor-core block attention: one CTA per (b, s), 8 warps.
// Stage Q/K/V hi/lo (bf16) in smem; per pass, warp w handles head 4*pass+w/2,
// row-half (w&1)*32. Scores & PV via hi/lo 3-MMA; softmax in registers.
// ---------------------------------------------------------------------------
#define AST 264                          // b16 row stride (conflict-free)
#define ATILE (64 * AST)                 // b16 elems per array
#define ASM_BYTES (6 * ATILE * 2)        // 202752 bytes

__global__ __launch_bounds__(256)
void attn_tc(float* __restrict__ outO, float* __restrict__ outW)
{
    extern __shared__ __nv_bfloat16 smb[];
    __nv_bfloat16* aQh = smb;
    __nv_bfloat16* aQl = smb + 1 * ATILE;
    __nv_bfloat16* aKh = smb + 2 * ATILE;
    __nv_bfloat16* aKl = smb + 3 * ATILE;
    __nv_bfloat16* aVh = smb + 4 * ATILE;
    __nv_bfloat16* aVl = smb + 5 * ATILE;

    const int bs  = blockIdx.x;
    const int tid = threadIdx.x;
    const size_t gbase = (size_t)bs * (NBLK * DIM);

    // ---- stage: 6 x (64 rows x 256 bf16) via cp.async ----
    {
        const __nv_bfloat16* srcs[6] = { g_Qh + gbase, g_Ql + gbase,
                                         g_Kh + gbase, g_Kl + gbase,
                                         g_Vh + gbase, g_Vl + gbase };
        #pragma unroll
        for (int a = 0; a < 6; a++) {
            uint32_t sb = smem_u32(smb + a * ATILE);
            #pragma unroll
            for (int t = 0; t < 8; t++) {
                int idx = t * 256 + tid;
                int r = idx >> 5, gseg = idx & 31;
                cpasync16(sb + (uint32_t)(r * AST + gseg * 8) * 2,
                          srcs[a] + r * DIM + gseg * 8);
            }
        }
        CP_COMMIT_WAIT();
        __syncthreads();
    }

    const uint32_t sQh = smem_u32(aQh), sQl = smem_u32(aQl);
    const uint32_t sKh = smem_u32(aKh), sKl = smem_u32(aKl);
    const uint32_t sVh = smem_u32(aVh), sVl = smem_u32(aVl);

    const int wid = tid >> 5, lane = tid & 31;
    const int g = lane >> 2, tq = lane & 3;
    const int b = bs >> 10, s0 = bs & 1023;
    const float scale = 0.17677669529663687f;   // 1/sqrt(32)

    #pragma unroll 1
    for (int pass = 0; pass < 2; pass++) {
        const int h = pass * 4 + (wid >> 1);
        const int rb = (wid & 1) * 32;
        const int hoff = h * DHD;

        // ---- Q A-fragments (hi & lo), 2 m-tiles x 2 k-blocks ----
        uint32_t qh[2][2][4], ql[2][2][4];
        #pragma unroll
        for (int mt = 0; mt < 2; mt++)
            #pragma unroll
            for (int kb = 0; kb < 2; kb++) {
                uint32_t ad = (uint32_t)((rb + 16 * mt + (lane & 15)) * AST
                              + hoff + 16 * kb + (lane >> 4) * 8) * 2;
                ldmx4(qh[mt][kb], sQh + ad);
                ldmx4(ql[mt][kb], sQl + ad);
            }

        // ---- scores S = Q K^T (hi/lo 3-MMA) ----
        float S[2][8][4];
        #pragma unroll
        for (int mt = 0; mt < 2; mt++)
            #pragma unroll
            for (int j = 0; j < 8; j++)
                #pragma unroll
                for (int q = 0; q < 4; q++) S[mt][j][q] = 0.f;

        #pragma unroll
        for (int jp = 0; jp < 4; jp++) {
            #pragma unroll
            for (int kb = 0; kb < 2; kb++) {
                // x4: n-tiles 2jp (r0,r1) and 2jp+1 (r2,r3)
                uint32_t ad = (uint32_t)((16 * jp + (lane & 7) + ((lane >> 4) & 1) * 8) * AST
                              + hoff + 16 * kb + ((lane >> 3) & 1) * 8) * 2;
                uint32_t kh4[4], kl4[4];
                ldmx4(kh4, sKh + ad);
                ldmx4(kl4, sKl + ad);
                #pragma unroll
                for (int mt = 0; mt < 2; mt++) {
                    mma16816(S[mt][2 * jp + 0], qh[mt][kb], kh4[0], kh4[1]);
                    mma16816(S[mt][2 * jp + 0], qh[mt][kb], kl4[0], kl4[1]);
                    mma16816(S[mt][2 * jp + 0], ql[mt][kb], kh4[0], kh4[1]);
                    mma16816(S[mt][2 * jp + 1], qh[mt][kb], kh4[2], kh4[3]);
                    mma16816(S[mt][2 * jp + 1], qh[mt][kb], kl4[2], kl4[3]);
                    mma16816(S[mt][2 * jp + 1], ql[mt][kb], kh4[2], kh4[3]);
                }
            }
        }

        // ---- softmax in fragment registers + write attn_weight ----
        const size_t wb = (((size_t)b * NH + h) * SS + s0) * (NBLK * NBLK);
        #pragma unroll
        for (int mt = 0; mt < 2; mt++) {
            float m0 = -1e30f, m1 = -1e30f;
            #pragma unroll
            for (int j = 0; j < 8; j++) {
                #pragma unroll
                for (int q = 0; q < 4; q++) S[mt][j][q] *= scale;
                m0 = fmaxf(m0, fmaxf(S[mt][j][0], S[mt][j][1]));
                m1 = fmaxf(m1, fmaxf(S[mt][j][2], S[mt][j][3]));
            }
            m0 = fmaxf(m0, __shfl_xor_sync(0xffffffffu, m0, 1));
            m0 = fmaxf(m0, __shfl_xor_sync(0xffffffffu, m0, 2));
            m1 = fmaxf(m1, __shfl_xor_sync(0xffffffffu, m1, 1));
            m1 = fmaxf(m1, __shfl_xor_sync(0xffffffffu, m1, 2));
            float s0a = 0.f, s1a = 0.f;
            #pragma unroll
            for (int j = 0; j < 8; j++) {
                S[mt][j][0] = __expf(S[mt][j][0] - m0); s0a += S[mt][j][0];
                S[mt][j][1] = __expf(S[mt][j][1] - m0); s0a += S[mt][j][1];
                S[mt][j][2] = __expf(S[mt][j][2] - m1); s1a += S[mt][j][2];
                S[mt][j][3] = __expf(S[mt][j][3] - m1); s1a += S[mt][j][3];
            }
            s0a += __shfl_xor_sync(0xffffffffu, s0a, 1);
            s0a += __shfl_xor_sync(0xffffffffu, s0a, 2);
            s1a += __shfl_xor_sync(0xffffffffu, s1a, 1);
            s1a += __shfl_xor_sync(0xffffffffu, s1a, 2);
            float i0 = 1.0f / s0a, i1 = 1.0f / s1a;
            const int n0 = rb + 16 * mt + g;
            #pragma unroll
            for (int j = 0; j < 8; j++) {
                S[mt][j][0] *= i0; S[mt][j][1] *= i0;
                S[mt][j][2] *= i1; S[mt][j][3] *= i1;
                *(float2*)&outW[wb + (size_t)n0 * NBLK + 8 * j + 2 * tq] =
                    make_float2(S[mt][j][0], S[mt][j][1]);
                *(float2*)&outW[wb + (size_t)(n0 + 8) * NBLK + 8 * j + 2 * tq] =
                    make_float2(S[mt][j][2], S[mt][j][3]);
            }
        }

        // ---- PV: out = P V (hi/lo 3-MMA); P A-frags built from S regs ----
        float o[2][4][4];
        #pragma unroll
        for (int mt = 0; mt < 2; mt++)
            #pragma unroll
            for (int nd = 0; nd < 4; nd++)
                #pragma unroll
                for (int q = 0; q < 4; q++) o[mt][nd][q] = 0.f;

        #pragma unroll
        for (int kb2 = 0; kb2 < 4; kb2++) {
            uint32_t pah[2][4], pal[2][4];
            #pragma unroll
            for (int mt = 0; mt < 2; mt++) {
                const float* sa = S[mt][2 * kb2];
                const float* sb2 = S[mt][2 * kb2 + 1];
                hilo2(sa[0],  sa[1],  pah[mt][0], pal[mt][0]);
                hilo2(sa[2],  sa[3],  pah[mt][1], pal[mt][1]);
                hilo2(sb2[0], sb2[1], pah[mt][2], pal[mt][2]);
                hilo2(sb2[2], sb2[3], pah[mt][3], pal[mt][3]);
            }
            #pragma unroll
            for (int ndp = 0; ndp < 2; ndp++) {
                // x4.trans: B-frags for n-tiles 2ndp (r0,r1) and 2ndp+1 (r2,r3)
                uint32_t ad = (uint32_t)((16 * kb2 + (lane & 7) + ((lane >> 3) & 1) * 8) * AST
                              + hoff + 16 * ndp + ((lane >> 4) & 1) * 8) * 2;
                uint32_t vh4[4], vl4[4];
                ldmx4t(vh4, sVh + ad);
                ldmx4t(vl4, sVl + ad);
                #pragma unroll
                for (int mt = 0; mt < 2; mt++) {
                    mma16816(o[mt][2 * ndp + 0], pah[mt], vh4[0], vh4[1]);
                    mma16816(o[mt][2 * ndp + 0], pah[mt], vl4[0], vl4[1]);
                    mma16816(o[mt][2 * ndp + 0], pal[mt], vh4[0], vh4[1]);
                    mma16816(o[mt][2 * ndp + 1], pah[mt], vh4[2], vh4[3]);
                    mma16816(o[mt][2 * ndp + 1], pah[mt], vl4[2], vl4[3]);
                    mma16816(o[mt][2 * ndp + 1], pal[mt], vh4[2], vh4[3]);
                }
            }
        }

        // ---- write attn_output ----
        #pragma unroll
        for (int mt = 0; mt < 2; mt++) {
            const int n0 = rb + 16 * mt + g;
            #pragma unroll
            for (int nd = 0; nd < 4; nd++) {
                const int cd = hoff + 8 * nd + 2 * tq;
                *(float2*)&outO[gbase + (size_t)n0 * DIM + cd] =
                    make_float2(o[mt][nd][0], o[mt][nd][1]);
                *(float2*)&outO[gbase + (size_t)(n0 + 8) * DIM + cd] =
                    make_float2(o[mt][nd][2], o[mt][nd][3]);
            }
        }
    }
}

// ---------------------------------------------------------------------------
// kernel_launch
// ---------------------------------------------------------------------------
extern "C" void kernel_launch(void* const* d_in, const int* in_sizes, int n_in,
                              void* d_out, int out_size)
{
    const float* query = (const float*)d_in[0];
    const float* key   = (const float*)d_in[1];
    const float* value = (const float*)d_in[2];
    const float* Wq    = (const float*)d_in[3];
    const float* bq    = (const float*)d_in[4];
    const float* Wk    = (const float*)d_in[5];
    const float* bk    = (const float*)d_in[6];
    const float* Wv    = (const float*)d_in[7];
    const float* bv    = (const float*)d_in[8];

    float* attn_out = (float*)d_out;
    float* attn_w   = (float*)d_out + (size_t)BB * SS * NBLK * DIM;

    cudaFuncSetAttribute(attn_tc, cudaFuncAttributeMaxDynamicSharedMemorySize,
                         ASM_BYTES);

    dim3 gg(DIM / 128, NROWS / 128);   // (2, 1024)
    convW<<<256, 256>>>(Wq);
    proj_mma<<<gg, 256>>>(query, bq, 0);
    convW<<<256, 256>>>(Wk);
    proj_mma<<<gg, 256>>>(key, bk, 1);
    convW<<<256, 256>>>(Wv);
    proj_mma<<<gg, 256>>>(value, bv, 2);

    attn_tc<<<BB * SS, 256, ASM_BYTES>>>(attn_out, attn_w);
}